// round 12
// baseline (speedup 1.0000x reference)
#include <cuda_runtime.h>
#include <math.h>

#define MAXD 2048
#define TILE 32
#define NTMAX (MAXD / TILE)     // 64
#define ETA 0.005f

// Disjoint partials: slot [p][j] = contribution of row-tile p to column/row j.
// Every slot written exactly once per launch -> no zeroing, no atomics, no fences.
__device__ float g_partM[NTMAX][MAXD];   // 512 KB
__device__ float g_partR[NTMAX][MAXD];   // 512 KB
__device__ float g_m[MAXD];              // m[j]           (pre-scaled by 1/D)
__device__ float g_rm[MAXD];             // rowmean[b] * ETA / D

// ---------------------------------------------------------------------------
// Kernel 1: symmetric strip-pair reduction, latency-optimized.
// Block = 4 tile-pairs: A-strip = x[I-tile, JB..JB+3 tiles] (32x128),
//                       B-strip = x[JB..JB+3 tiles, I-tile] (128x32).
//  * 8 front-batched LDG.128 per thread (MLP=8 covers DRAM latency)
//  * ONE __syncthreads; zero shared reductions
//  * warp w: pair j = w>>1, pass = w&1; each thread owns one output:
//      pass1 (col l of pair j): partM[I][J*32+l] = sum_u A[u][32j+l]*B[32j+l][u]
//                               partR[I][J*32+l] = sum_u B[32j+l][u]
//      pass2 (row l of pair j): partM[J][I*32+l] = sum_v A[l][32j+v]*B[32j+v][l]
//                               partR[J][I*32+l] = sum_v A[l][32j+v]
//  * diag pair (J==I): pass1 only;  straddle pair (J<I): skipped.
// Shared layout (padded, all access patterns conflict-free):
//   As4[32][33] float4 (row stride 132 words), Bs4[128][9] float4 (stride 36).
// ---------------------------------------------------------------------------
__global__ void __launch_bounds__(256) hebb_tile_kernel(
    const float* __restrict__ x, int D)
{
    const int I  = blockIdx.y;          // row-tile
    const int JB = blockIdx.x << 2;     // first col-tile of this strip
    if (JB + 3 < I) return;             // fully lower-triangle: no-op block

    __shared__ float4 As4[32][33];
    __shared__ float4 Bs4[128][9];

    const int tid = threadIdx.x;
    const int r   = tid >> 3;           // 0..31
    const int c8  = tid & 7;            // 0..7

    // A-strip rows: 4 independent float4 loads (coalesced per 8-lane group).
    const float* arow = x + (size_t)(I * 32 + r) * D + JB * 32;
    #pragma unroll
    for (int jj = 0; jj < 4; jj++)
        As4[r][jj * 8 + c8] =
            *reinterpret_cast<const float4*>(arow + ((jj * 8 + c8) << 2));
    // B-strip rows: 4 more independent loads.
    #pragma unroll
    for (int jj = 0; jj < 4; jj++) {
        const int rb = jj * 32 + r;
        Bs4[rb][c8] = *reinterpret_cast<const float4*>(
            x + (size_t)(JB * 32 + rb) * D + I * 32 + (c8 << 2));
    }
    __syncthreads();

    const int j     = tid >> 6;         // pair 0..3
    const int which = (tid >> 5) & 1;   // 0 = pass1, 1 = pass2 (warp-uniform)
    const int l     = tid & 31;
    const int J     = JB + j;
    if (J < I) return;                  // straddle pair

    const float* Af = reinterpret_cast<const float*>(As4);
    const float* Bf = reinterpret_cast<const float*>(Bs4);

    if (which == 0) {
        // Column l of pair j.
        float sm = 0.0f, sr = 0.0f;
        const int acol = 32 * j + l;
        const float4* brow = Bs4[32 * j + l];       // LDS.128, conflict-free
        #pragma unroll
        for (int q = 0; q < 8; q++) {
            const float4 b = brow[q];
            const int u = q << 2;
            sm += Af[(u + 0) * 132 + acol] * b.x + Af[(u + 1) * 132 + acol] * b.y
                + Af[(u + 2) * 132 + acol] * b.z + Af[(u + 3) * 132 + acol] * b.w;
            sr += (b.x + b.y) + (b.z + b.w);
        }
        g_partM[I][J * 32 + l] = sm;
        g_partR[I][J * 32 + l] = sr;
    } else if (J > I) {
        // Row l of pair j.
        float sm = 0.0f, sr = 0.0f;
        const float4* arow4 = As4[l];
        #pragma unroll
        for (int q = 0; q < 8; q++) {
            const float4 a = arow4[8 * j + q];      // LDS.128, conflict-free
            const int v = 32 * j + (q << 2);
            sm += a.x * Bf[(v + 0) * 36 + l] + a.y * Bf[(v + 1) * 36 + l]
                + a.z * Bf[(v + 2) * 36 + l] + a.w * Bf[(v + 3) * 36 + l];
            sr += (a.x + a.y) + (a.z + a.w);
        }
        g_partM[J][I * 32 + l] = sm;
        g_partR[J][I * 32 + l] = sr;
    }
}

// ---------------------------------------------------------------------------
// Kernel 2: partials reduction, parallel over columns AND p.
// ---------------------------------------------------------------------------
__global__ void __launch_bounds__(256) hebb_reduce_kernel(int NT, float invD)
{
    __shared__ float sM[8][33];
    __shared__ float sR[8][33];
    const int lane = threadIdx.x & 31;
    const int g    = threadIdx.x >> 5;
    const int j    = blockIdx.x * 32 + lane;

    float sm = 0.0f, sr = 0.0f;
    for (int p = g; p < NT; p += 8) {
        sm += g_partM[p][j];
        sr += g_partR[p][j];
    }
    sM[g][lane] = sm;
    sR[g][lane] = sr;
    __syncthreads();
    if (threadIdx.x < 32) {
        float m = 0.0f, r = 0.0f;
        #pragma unroll
        for (int k = 0; k < 8; k++) { m += sM[k][threadIdx.x]; r += sR[k][threadIdx.x]; }
        const int jj = blockIdx.x * 32 + threadIdx.x;
        g_m[jj]  = m * invD;
        g_rm[jj] = r * (invD * ETA);
    }
}

// ---------------------------------------------------------------------------
// Kernel 3: elementwise outputs. 1024 blocks, rows 2*bid and 2*bid+1,
// all loads front-batched.
// ---------------------------------------------------------------------------
template<int COLS4, bool NK>
__global__ void __launch_bounds__(256) hebb_ew_kernel_s(
    const float* __restrict__ x, const float* __restrict__ kmat,
    float* __restrict__ y, float* __restrict__ nk)
{
    const int tid = threadIdx.x;
    const int c0 = tid, c1 = tid + 256;
    const int row = blockIdx.x * 2;
    const size_t b0 = (size_t)row * COLS4;
    const size_t b1 = b0 + COLS4;

    const float4* m4 = reinterpret_cast<const float4*>(g_m);
    const float4* k0 = reinterpret_cast<const float4*>(kmat) + b0;
    const float4* k1 = reinterpret_cast<const float4*>(kmat) + b1;
    const float4* x0 = reinterpret_cast<const float4*>(x) + b0;
    const float4* x1 = reinterpret_cast<const float4*>(x) + b1;

    float4 ma = m4[c0], mb = m4[c1];
    float4 ka0 = k0[c0], kb0 = k0[c1];
    float4 ka1 = k1[c0], kb1 = k1[c1];
    float4 xa0, xb0, xa1, xb1;
    if (NK) { xa0 = x0[c0]; xb0 = x0[c1]; xa1 = x1[c0]; xb1 = x1[c1]; }
    const float rm0 = g_rm[row];
    const float rm1 = g_rm[row + 1];

    float4* y0 = reinterpret_cast<float4*>(y) + b0;
    float4* y1 = reinterpret_cast<float4*>(y) + b1;

    float4 v;
    v.x = ka0.x * ma.x; v.y = ka0.y * ma.y; v.z = ka0.z * ma.z; v.w = ka0.w * ma.w;
    y0[c0] = v;
    v.x = kb0.x * mb.x; v.y = kb0.y * mb.y; v.z = kb0.z * mb.z; v.w = kb0.w * mb.w;
    y0[c1] = v;
    v.x = ka1.x * ma.x; v.y = ka1.y * ma.y; v.z = ka1.z * ma.z; v.w = ka1.w * ma.w;
    y1[c0] = v;
    v.x = kb1.x * mb.x; v.y = kb1.y * mb.y; v.z = kb1.z * mb.z; v.w = kb1.w * mb.w;
    y1[c1] = v;

    if (NK) {
        float4* n0 = reinterpret_cast<float4*>(nk) + b0;
        float4* n1 = reinterpret_cast<float4*>(nk) + b1;
        v.x = fmaf(rm0, xa0.x, ka0.x); v.y = fmaf(rm0, xa0.y, ka0.y);
        v.z = fmaf(rm0, xa0.z, ka0.z); v.w = fmaf(rm0, xa0.w, ka0.w);
        n0[c0] = v;
        v.x = fmaf(rm0, xb0.x, kb0.x); v.y = fmaf(rm0, xb0.y, kb0.y);
        v.z = fmaf(rm0, xb0.z, kb0.z); v.w = fmaf(rm0, xb0.w, kb0.w);
        n0[c1] = v;
        v.x = fmaf(rm1, xa1.x, ka1.x); v.y = fmaf(rm1, xa1.y, ka1.y);
        v.z = fmaf(rm1, xa1.z, ka1.z); v.w = fmaf(rm1, xa1.w, ka1.w);
        n1[c0] = v;
        v.x = fmaf(rm1, xb1.x, kb1.x); v.y = fmaf(rm1, xb1.y, kb1.y);
        v.z = fmaf(rm1, xb1.z, kb1.z); v.w = fmaf(rm1, xb1.w, kb1.w);
        n1[c1] = v;
    }
}

// Generic fallback (runtime D4).
__global__ void __launch_bounds__(256) hebb_ew_kernel_g(
    const float* __restrict__ x, const float* __restrict__ kmat,
    float* __restrict__ y, float* __restrict__ nk, int D4, int n4, int write_nk)
{
    int idx = blockIdx.x * 256 + threadIdx.x;
    if (idx >= n4) return;
    const int col4 = idx % D4;
    const int row  = idx / D4;
    float4 kv = reinterpret_cast<const float4*>(kmat)[idx];
    float4 mv = reinterpret_cast<const float4*>(g_m)[col4];
    float4 yv;
    yv.x = kv.x * mv.x; yv.y = kv.y * mv.y; yv.z = kv.z * mv.z; yv.w = kv.w * mv.w;
    reinterpret_cast<float4*>(y)[idx] = yv;
    if (write_nk) {
        float rm = g_rm[row];
        float4 xv = reinterpret_cast<const float4*>(x)[idx];
        float4 nv;
        nv.x = fmaf(rm, xv.x, kv.x); nv.y = fmaf(rm, xv.y, kv.y);
        nv.z = fmaf(rm, xv.z, kv.z); nv.w = fmaf(rm, xv.w, kv.w);
        reinterpret_cast<float4*>(nk)[idx] = nv;
    }
}

extern "C" void kernel_launch(void* const* d_in, const int* in_sizes, int n_in,
                              void* d_out, int out_size)
{
    if (n_in < 2 || !d_in || !d_out || !in_sizes) return;

    const float* x    = (const float*)d_in[0];
    const float* kmat = (const float*)d_in[1];
    float* out        = (float*)d_out;

    const int n = in_sizes[0];           // D*D
    int D = 1;
    while (D < MAXD && D * D < n) D++;   // D = 2048 here
    if (D * D != n || (D % 128) != 0) return;

    const int NT = D / TILE;              // 64
    const int write_nk = (out_size >= 2 * n) ? 1 : 0;
    const float invD = 1.0f / (float)D;

    float* y  = out;
    float* nk = out + n;

    dim3 tgrid(NT / 4, NT);               // (16, 64)
    hebb_tile_kernel<<<tgrid, 256>>>(x, D);
    hebb_reduce_kernel<<<D / 32, 256>>>(NT, invD);

    if (D == 2048) {
        if (write_nk)
            hebb_ew_kernel_s<512, true><<<1024, 256>>>(x, kmat, y, nk);
        else
            hebb_ew_kernel_s<512, false><<<1024, 256>>>(x, kmat, y, nk);
    } else {
        const int n4 = n >> 2;
        hebb_ew_kernel_g<<<(n4 + 255) / 256, 256>>>(x, kmat, y, nk, D >> 2, n4, write_nk);
    }
}